// round 4
// baseline (speedup 1.0000x reference)
#include <cuda_runtime.h>

// Problem constants
#define BB   4096
#define TT   50
#define OBS  64
#define ACTD 16
#define DIN  80      // OBS + ACT
#define HH   256
#define G4   1024    // 4*H
#define NL   5
#define OUTD 64

// Kernel config
#define RPB  32            // batch rows per CTA
#define NCTA (BB / RPB)    // 128
#define NTH  256
#define SAS  36            // sA row stride in floats
#define AROWS 336          // 80 x-rows + 256 h-rows

// Shared memory (floats)
#define SZ_SA   (AROWS * SAS)    // 12096
#define SZ_SHN  (HH * SAS)       //  9216
#define SZ_SB   (G4)             //  1024
#define OFF_SA  0
#define OFF_SHN (OFF_SA + SZ_SA)
#define OFF_SB  (OFF_SHN + SZ_SHN)
#define SMEM_FLOATS (OFF_SB + SZ_SB)   // 22336 floats = 89344 B

typedef unsigned long long ull;

__device__ __forceinline__ float sigf(float x) {
    return __fdividef(1.0f, 1.0f + __expf(-x));
}

// packed f32x2 (sm_103a FFMA2 — PTX-only path)
__device__ __forceinline__ void ffma2(ull &d, ull a, ull b) {
    asm("fma.rn.f32x2 %0, %1, %2, %0;" : "+l"(d) : "l"(a), "l"(b));
}
__device__ __forceinline__ ull pk2(float lo, float hi) {
    ull r; asm("mov.b64 %0, {%1, %2};" : "=l"(r) : "f"(lo), "f"(hi)); return r;
}
__device__ __forceinline__ void upk2(ull v, float &lo, float &hi) {
    asm("mov.b64 {%0, %1}, %2;" : "=f"(lo), "=f"(hi) : "l"(v));
}

__device__ __forceinline__ void gatef(float zi, float zf, float zg, float zo,
                                      float &c, float* __restrict__ sHN,
                                      int hk, int row)
{
    const float ig = sigf(zi);
    const float fg = sigf(zf);
    const float gg = zg * sigf(zg);       // silu
    const float og = sigf(zo);
    const float cn = fg * c + ig * gg;
    c = cn;
    sHN[hk * SAS + row] = og * cn * sigf(cn);  // o * silu(c_new)
}

__global__ void __launch_bounds__(NTH, 1)
lstm_fwd_kernel(const float* __restrict__ traj, const float* __restrict__ act,
                const float* __restrict__ Wi,   const float* __restrict__ Wh,
                const float* __restrict__ bh,   const float* __restrict__ mlpW,
                const float* __restrict__ mlpB, const float* __restrict__ Wout,
                const float* __restrict__ bout, float* __restrict__ out)
{
    extern __shared__ float sm[];
    float* sA  = sm + OFF_SA;    // [336][36] k-major: 0..79 x, 80..335 h (or MLP act)
    float* sHN = sm + OFF_SHN;   // [256][36]
    float* sB  = sm + OFF_SB;    // [1024]

    const int tid  = threadIdx.x;
    const int row0 = blockIdx.x * RPB;
    const int rgrp = tid & 7;        // 8 row groups x 4 rows
    const int cgrp = tid >> 3;       // 0..31, each owns 4 hk cols per half
    const int r0   = rgrp << 2;

    // cell state: creg[half*16 + c*4 + r], c in 0..3 (hk cols), r rows
    float creg[32];
    #pragma unroll
    for (int i = 0; i < 32; ++i) creg[i] = 0.0f;

    // init: zero h region of sA, cache bh, preload x(0)
    for (int i = tid; i < HH * SAS; i += NTH) sA[DIN * SAS + i] = 0.0f;
    for (int i = tid; i < G4; i += NTH) sB[i] = bh[i];
    for (int i = tid; i < DIN * RPB; i += NTH) {
        const int r = i & 31, k = i >> 5;
        const int row = row0 + r;
        float v;
        if (k < OBS) v = traj[((size_t)row * TT) * OBS + k];
        else         v = act [((size_t)row * TT) * ACTD + (k - OBS)];
        sA[k * SAS + r] = v;
    }
    __syncthreads();

    // ============================ LSTM over time ============================
    for (int t = 0; t < TT; ++t) {
        #pragma unroll
        for (int half = 0; half < 2; ++half) {
            const int hk0 = (half << 7) + (cgrp << 2);
            const float* wI = Wi + hk0;    // + k*1024 + g*256
            const float* wH = Wh + hk0;

            // acc[g*8 + cp*4 + r]: gate g, col-pair cp (cols 2cp,2cp+1), row r
            ull acc[32];
            #pragma unroll
            for (int i = 0; i < 32; ++i) acc[i] = 0ull;

            // x part: k = 0..79
            #pragma unroll 4
            for (int k = 0; k < DIN; ++k) {
                const float4 a = *(const float4*)(sA + k * SAS + r0);
                const ull a0 = pk2(a.x, a.x), a1 = pk2(a.y, a.y);
                const ull a2 = pk2(a.z, a.z), a3 = pk2(a.w, a.w);
                const float* wr = wI + (size_t)k * G4;
                #pragma unroll
                for (int g = 0; g < 4; ++g) {
                    const ulonglong2 w = *(const ulonglong2*)(wr + (g << 8));
                    ffma2(acc[g * 8 + 0], w.x, a0);
                    ffma2(acc[g * 8 + 1], w.x, a1);
                    ffma2(acc[g * 8 + 2], w.x, a2);
                    ffma2(acc[g * 8 + 3], w.x, a3);
                    ffma2(acc[g * 8 + 4], w.y, a0);
                    ffma2(acc[g * 8 + 5], w.y, a1);
                    ffma2(acc[g * 8 + 6], w.y, a2);
                    ffma2(acc[g * 8 + 7], w.y, a3);
                }
            }
            // h part: k = 0..255
            #pragma unroll 4
            for (int k = 0; k < HH; ++k) {
                const float4 a = *(const float4*)(sA + (DIN + k) * SAS + r0);
                const ull a0 = pk2(a.x, a.x), a1 = pk2(a.y, a.y);
                const ull a2 = pk2(a.z, a.z), a3 = pk2(a.w, a.w);
                const float* wr = wH + (size_t)k * G4;
                #pragma unroll
                for (int g = 0; g < 4; ++g) {
                    const ulonglong2 w = *(const ulonglong2*)(wr + (g << 8));
                    ffma2(acc[g * 8 + 0], w.x, a0);
                    ffma2(acc[g * 8 + 1], w.x, a1);
                    ffma2(acc[g * 8 + 2], w.x, a2);
                    ffma2(acc[g * 8 + 3], w.x, a3);
                    ffma2(acc[g * 8 + 4], w.y, a0);
                    ffma2(acc[g * 8 + 5], w.y, a1);
                    ffma2(acc[g * 8 + 6], w.y, a2);
                    ffma2(acc[g * 8 + 7], w.y, a3);
                }
            }

            // gate epilogue — thread owns (rows r0..r0+3, cols hk0..hk0+3)
            const float4 bi4 = *(const float4*)(sB + hk0);
            const float4 bf4 = *(const float4*)(sB + 256 + hk0);
            const float4 bg4 = *(const float4*)(sB + 512 + hk0);
            const float4 bo4 = *(const float4*)(sB + 768 + hk0);
            const float bi[4] = {bi4.x, bi4.y, bi4.z, bi4.w};
            const float bf[4] = {bf4.x, bf4.y, bf4.z, bf4.w};
            const float bg[4] = {bg4.x, bg4.y, bg4.z, bg4.w};
            const float bo[4] = {bo4.x, bo4.y, bo4.z, bo4.w};
            #pragma unroll
            for (int cp = 0; cp < 2; ++cp) {
                #pragma unroll
                for (int r = 0; r < 4; ++r) {
                    float zi0, zi1, zf0, zf1, zg0, zg1, zo0, zo1;
                    upk2(acc[0 * 8 + cp * 4 + r], zi0, zi1);
                    upk2(acc[1 * 8 + cp * 4 + r], zf0, zf1);
                    upk2(acc[2 * 8 + cp * 4 + r], zg0, zg1);
                    upk2(acc[3 * 8 + cp * 4 + r], zo0, zo1);
                    const int ca = cp * 2, cb = cp * 2 + 1;
                    gatef(zi0 + bi[ca], zf0 + bf[ca], zg0 + bg[ca], zo0 + bo[ca],
                          creg[half * 16 + ca * 4 + r], sHN, hk0 + ca, r0 + r);
                    gatef(zi1 + bi[cb], zf1 + bf[cb], zg1 + bg[cb], zo1 + bo[cb],
                          creg[half * 16 + cb * 4 + r], sHN, hk0 + cb, r0 + r);
                }
            }
        }
        __syncthreads();

        // commit h_new -> sA h rows; preload x(t+1)
        for (int i = tid; i < HH * 8; i += NTH) {
            const int c = i >> 3, r4 = (i & 7) << 2;
            *(float4*)(sA + (DIN + c) * SAS + r4) = *(const float4*)(sHN + c * SAS + r4);
        }
        if (t + 1 < TT) {
            for (int i = tid; i < DIN * RPB; i += NTH) {
                const int r = i & 31, k = i >> 5;
                const int row = row0 + r;
                float v;
                if (k < OBS) v = traj[((size_t)row * TT + t + 1) * OBS + k];
                else         v = act [((size_t)row * TT + t + 1) * ACTD + (k - OBS)];
                sA[k * SAS + r] = v;
            }
        }
        __syncthreads();
    }

    // ============================ MLP head ============================
    // Thread owns 4 rows x 8 cols: c0 = cgrp*8. Per kk: 1 LDS.128 + 2 LDG.128.
    for (int l = 0; l < NL; ++l) {
        const float* Wl = mlpW + (size_t)l * HH * HH + (cgrp << 3);
        ull acc[16];                      // [cp(4)][r(4)]
        #pragma unroll
        for (int i = 0; i < 16; ++i) acc[i] = 0ull;

        #pragma unroll 4
        for (int k = 0; k < HH; ++k) {
            const float4 a = *(const float4*)(sA + (DIN + k) * SAS + r0);
            const ull a0 = pk2(a.x, a.x), a1 = pk2(a.y, a.y);
            const ull a2 = pk2(a.z, a.z), a3 = pk2(a.w, a.w);
            const ulonglong2 wA = *(const ulonglong2*)(Wl + (size_t)k * HH);
            const ulonglong2 wB = *(const ulonglong2*)(Wl + (size_t)k * HH + 4);
            ffma2(acc[ 0], wA.x, a0); ffma2(acc[ 1], wA.x, a1);
            ffma2(acc[ 2], wA.x, a2); ffma2(acc[ 3], wA.x, a3);
            ffma2(acc[ 4], wA.y, a0); ffma2(acc[ 5], wA.y, a1);
            ffma2(acc[ 6], wA.y, a2); ffma2(acc[ 7], wA.y, a3);
            ffma2(acc[ 8], wB.x, a0); ffma2(acc[ 9], wB.x, a1);
            ffma2(acc[10], wB.x, a2); ffma2(acc[11], wB.x, a3);
            ffma2(acc[12], wB.y, a0); ffma2(acc[13], wB.y, a1);
            ffma2(acc[14], wB.y, a2); ffma2(acc[15], wB.y, a3);
        }
        __syncthreads();   // all reads of sA done before overwrite
        // silu epilogue -> sHN
        const int c0 = cgrp << 3;
        #pragma unroll
        for (int cp = 0; cp < 4; ++cp) {
            const float b0 = mlpB[l * HH + c0 + cp * 2];
            const float b1 = mlpB[l * HH + c0 + cp * 2 + 1];
            #pragma unroll
            for (int r = 0; r < 4; ++r) {
                float v0, v1;
                upk2(acc[cp * 4 + r], v0, v1);
                v0 += b0; v1 += b1;
                sHN[(c0 + cp * 2 + 0) * SAS + r0 + r] = v0 * sigf(v0);
                sHN[(c0 + cp * 2 + 1) * SAS + r0 + r] = v1 * sigf(v1);
            }
        }
        __syncthreads();
        for (int i = tid; i < HH * 8; i += NTH) {
            const int c = i >> 3, r4 = (i & 7) << 2;
            *(float4*)(sA + (DIN + c) * SAS + r4) = *(const float4*)(sHN + c * SAS + r4);
        }
        __syncthreads();
    }

    // ---- output layer: [32x256] @ [256x64] + bout; thread: 4 rows x 2 cols
    {
        const int c0 = cgrp << 1;
        const float* Wo = Wout + c0;

        ull acco[4];
        #pragma unroll
        for (int i = 0; i < 4; ++i) acco[i] = 0ull;

        #pragma unroll 8
        for (int k = 0; k < HH; ++k) {
            const float4 a = *(const float4*)(sA + (DIN + k) * SAS + r0);
            const ull w = *(const ull*)(Wo + (size_t)k * OUTD);
            ffma2(acco[0], w, pk2(a.x, a.x));
            ffma2(acco[1], w, pk2(a.y, a.y));
            ffma2(acco[2], w, pk2(a.z, a.z));
            ffma2(acco[3], w, pk2(a.w, a.w));
        }
        const float b0 = bout[c0], b1 = bout[c0 + 1];
        #pragma unroll
        for (int r = 0; r < 4; ++r) {
            float v0, v1; upk2(acco[r], v0, v1);
            out[(size_t)(row0 + r0 + r) * OUTD + c0]     = v0 + b0;
            out[(size_t)(row0 + r0 + r) * OUTD + c0 + 1] = v1 + b1;
        }
    }
}

extern "C" void kernel_launch(void* const* d_in, const int* in_sizes, int n_in,
                              void* d_out, int out_size)
{
    const float* traj = (const float*)d_in[0];
    const float* act  = (const float*)d_in[1];
    const float* Wi   = (const float*)d_in[2];
    const float* Wh   = (const float*)d_in[3];
    const float* bh   = (const float*)d_in[4];
    const float* mlpW = (const float*)d_in[5];
    const float* mlpB = (const float*)d_in[6];
    const float* Wout = (const float*)d_in[7];
    const float* bout = (const float*)d_in[8];
    float* out = (float*)d_out;

    cudaFuncSetAttribute(lstm_fwd_kernel,
                         cudaFuncAttributeMaxDynamicSharedMemorySize,
                         SMEM_FLOATS * (int)sizeof(float));
    lstm_fwd_kernel<<<NCTA, NTH, SMEM_FLOATS * sizeof(float)>>>(
        traj, act, Wi, Wh, bh, mlpW, mlpB, Wout, bout, out);
}